// round 16
// baseline (speedup 1.0000x reference)
#include <cuda_runtime.h>
#include <cstdint>

// Problem constants
#define NGRAPH 128
#define NODES  256
#define CH     64
#define ADJ_ELEMS   ((size_t)NGRAPH * NODES * NODES)   // 8388608
#define F_ELEMS     ((size_t)NGRAPH * NODES * CH)      // 2097152
#define F_BASE      (3 * ADJ_ELEMS)                    // 25165824
#define STR  72   // sZ/sW row stride (floats); LDS.64 conflict-free (see R7)
#define BSTR 40   // bf16 tile row stride (u32); 20 8B-words == 4 (mod 16): conflict-free

// Inter-kernel scratch: F in bf16x2 pairs, pair-permuted layout, dense 32 u32/row.
__device__ uint32_t g_fbf16[3 * NGRAPH * NODES * 32];

// k-dimension permutation (f32 buffers): (k, k+4) adjacent -> LDS.64.
__device__ __forceinline__ int posk(int k) {
    return (k & ~7) + ((k & 3) << 1) + ((k >> 2) & 1);
}

__device__ __forceinline__ float tf32r(float x) {
    uint32_t u;
    asm("cvt.rna.tf32.f32 %0, %1;" : "=r"(u) : "f"(x));
    return __uint_as_float(u);
}

__device__ __forceinline__ void mma_tf32(float d[4], const uint32_t a[4], const uint32_t b[2]) {
    asm volatile(
        "mma.sync.aligned.m16n8k8.row.col.f32.tf32.tf32.f32 "
        "{%0,%1,%2,%3},{%4,%5,%6,%7},{%8,%9},{%0,%1,%2,%3};\n"
        : "+f"(d[0]), "+f"(d[1]), "+f"(d[2]), "+f"(d[3])
        : "r"(a[0]), "r"(a[1]), "r"(a[2]), "r"(a[3]),
          "r"(b[0]), "r"(b[1]));
}

__device__ __forceinline__ void mma_bf16(float d[4], const uint32_t a[4], const uint32_t b[2]) {
    asm volatile(
        "mma.sync.aligned.m16n8k16.row.col.f32.bf16.bf16.f32 "
        "{%0,%1,%2,%3},{%4,%5,%6,%7},{%8,%9},{%0,%1,%2,%3};\n"
        : "+f"(d[0]), "+f"(d[1]), "+f"(d[2]), "+f"(d[3])
        : "r"(a[0]), "r"(a[1]), "r"(a[2]), "r"(a[3]),
          "r"(b[0]), "r"(b[1]));
}

// sigmoid(x) = 0.5*tanh(x/2)+0.5 — single MUFU.
__device__ __forceinline__ float sigmoid_fast(float x) {
    float t;
    asm("tanh.approx.f32 %0, %1;" : "=f"(t) : "f"(x * 0.5f));
    return fmaf(t, 0.5f, 0.5f);
}

// pack {lo,hi} f32 -> bf16x2 (lo in bits[15:0])
__device__ __forceinline__ uint32_t pack_bf16(float lo, float hi) {
    uint32_t d;
    asm("cvt.rn.bf16x2.f32 %0, %1, %2;" : "=r"(d) : "f"(hi), "f"(lo));
    return d;
}

// ---------------------------------------------------------------------------
// Kernel 1: MLP (R14 path verbatim; F fp32 outputs bit-identical).
// Layer-2 epilogue writes pair-permuted bf16x2 F into g_fbf16 (dense 32 u32/row)
// instead of smem. 512 threads, grid (128,3), smem 111104 B.
// ---------------------------------------------------------------------------
__global__ void __launch_bounds__(512, 1) mlp_kernel(
    const float* __restrict__ z,
    const float* __restrict__ Wa1, const float* __restrict__ ba1,
    const float* __restrict__ Wa2, const float* __restrict__ ba2,
    const float* __restrict__ Wb1, const float* __restrict__ bb1,
    const float* __restrict__ Wb2, const float* __restrict__ bb2,
    const float* __restrict__ Wt1, const float* __restrict__ bt1,
    const float* __restrict__ Wt2, const float* __restrict__ bt2,
    float* __restrict__ out)
{
    extern __shared__ __align__(16) float smem[];
    float* sZ    = smem;                  // [256][STR], k-permuted f32
    float* sW    = smem + 256 * STR;      // [2][64][STR] tf32 weights
    float* sBias = sW + 2 * 64 * STR;     // [128]

    const int g    = blockIdx.x;
    const int type = blockIdx.y;

    const float *W1, *B1, *W2, *B2;
    if (type == 0)      { W1 = Wa1; B1 = ba1; W2 = Wa2; B2 = ba2; }
    else if (type == 1) { W1 = Wb1; B1 = bb1; W2 = Wb2; B2 = bb2; }
    else                { W1 = Wt1; B1 = bt1; W2 = Wt2; B2 = bt2; }

    const int tid = threadIdx.x;
    const int warp = tid >> 5, lane = tid & 31;
    const int g8 = lane >> 2, q = lane & 3;

    // Phase 0: loads
    const float* zG = z + (size_t)g * NODES * CH;
    for (int i = tid; i < NODES * CH / 4; i += 512) {
        int r = i >> 4, c4 = (i & 15) * 4;
        float4 v = *(const float4*)&zG[r * CH + c4];
        float* row = &sZ[r * STR];
        row[posk(c4 + 0)] = v.x;
        row[posk(c4 + 1)] = v.y;
        row[posk(c4 + 2)] = v.z;
        row[posk(c4 + 3)] = v.w;
    }
#pragma unroll 1
    for (int l = 0; l < 2; ++l) {
        const float* W = l ? W2 : W1;
        float* w = sW + l * 64 * STR;
        for (int i = tid; i < 64 * 64; i += 512) {
            int k = i >> 6, n = i & 63;
            w[n * STR + posk(k)] = tf32r(W[i]);
        }
    }
    if (tid < 64)       sBias[tid] = B1[tid];
    else if (tid < 128) sBias[tid] = B2[tid - 64];
    __syncthreads();

    // Phase 1: MLP (warp-private 16 rows, no block syncs)
    const int row0 = warp * 16;
    const int kq2 = 2 * q;
    float* __restrict__ fout = out + F_BASE + (size_t)type * F_ELEMS
                                   + (size_t)g * NODES * CH;
    uint32_t* __restrict__ fb = g_fbf16
        + ((size_t)(type * NGRAPH + g) * NODES) * 32;

#pragma unroll 1
    for (int l = 0; l < 2; ++l) {
        const float* Wt   = sW + l * 64 * STR;
        const float* bias = sBias + l * 64;

        float acc[8][4];
#pragma unroll
        for (int nt = 0; nt < 8; ++nt)
#pragma unroll
            for (int e = 0; e < 4; ++e) acc[nt][e] = 0.0f;

#pragma unroll
        for (int k0 = 0; k0 < 8; ++k0) {
            const int kp = k0 * 8 + kq2;
            float2 la = *(const float2*)&sZ[(row0 + g8)     * STR + kp];
            float2 lb = *(const float2*)&sZ[(row0 + g8 + 8) * STR + kp];
            uint32_t af[4];
            af[0] = __float_as_uint(tf32r(la.x));
            af[1] = __float_as_uint(tf32r(lb.x));
            af[2] = __float_as_uint(tf32r(la.y));
            af[3] = __float_as_uint(tf32r(lb.y));
#pragma unroll
            for (int nt = 0; nt < 8; ++nt) {
                float2 wb = *(const float2*)&Wt[(nt * 8 + g8) * STR + kp];
                uint32_t bf[2] = {__float_as_uint(wb.x), __float_as_uint(wb.y)};
                mma_tf32(acc[nt], af, bf);
            }
        }
        __syncwarp();

#pragma unroll
        for (int nt = 0; nt < 8; ++nt) {
            const int c0 = nt * 8 + 2 * q;
            float v0 = fmaxf(acc[nt][0] + bias[c0],     0.0f);
            float v1 = fmaxf(acc[nt][1] + bias[c0 + 1], 0.0f);
            float v2 = fmaxf(acc[nt][2] + bias[c0],     0.0f);
            float v3 = fmaxf(acc[nt][3] + bias[c0 + 1], 0.0f);
            if (l == 0) {
                const int p0 = posk(c0), p1 = posk(c0 + 1);
                float* rA = &sZ[(row0 + g8) * STR];
                float* rB = &sZ[(row0 + g8 + 8) * STR];
                rA[p0] = v0; rA[p1] = v1;
                rB[p0] = v2; rB[p1] = v3;
            } else {
                // F: fp32 -> out (bit-identical); bf16x2 pair -> scratch
                *(float2*)&fout[(size_t)(row0 + g8)     * CH + c0] = make_float2(v0, v1);
                *(float2*)&fout[(size_t)(row0 + g8 + 8) * CH + c0] = make_float2(v2, v3);
                const int p2 = (nt >> 1) * 8 + 2 * q + (nt & 1);
                fb[(row0 + g8)     * 32 + p2] = pack_bf16(v0, v1);
                fb[(row0 + g8 + 8) * 32 + p2] = pack_bf16(v2, v3);
            }
        }
        __syncwarp();
    }
}

// ---------------------------------------------------------------------------
// Kernel 2: adjacency, fine-grained. One CTA = one 128(m) x 64(n) tile.
// grid (8, 128, 3) = 3072 CTAs, 256 threads (8 warps), ~30.7 KB smem,
// target 3 CTAs/SM (24 warps) for latency hiding + fine tail quantization.
// Warp tile 32x32: mt=2, nt=4, acc = 32 regs. Same bf16 fragment math and
// k-chain order as R14 -> adjacency values bit-identical.
// ---------------------------------------------------------------------------
__global__ void __launch_bounds__(256, 3) adj_kernel(float* __restrict__ out)
{
    __shared__ __align__(16) uint32_t sA[128 * BSTR];
    __shared__ __align__(16) uint32_t sBt[64 * BSTR];

    const int tile = blockIdx.x;        // 0..7: tm = tile>>2, tn = tile&3
    const int g    = blockIdx.y;
    const int type = blockIdx.z;
    const int tm = tile >> 2, tn = tile & 3;

    const uint32_t* __restrict__ src = g_fbf16
        + ((size_t)(type * NGRAPH + g) * NODES) * 32;

    const int tid = threadIdx.x;
    const int warp = tid >> 5, lane = tid & 31;
    const int g8 = lane >> 2, q = lane & 3;

    // Load A block (128 rows) and B block (64 rows), coalesced uint4.
    for (int i = tid; i < 128 * 8; i += 256) {
        int r = i >> 3, c4 = (i & 7) * 4;
        uint4 v = *(const uint4*)&src[(tm * 128 + r) * 32 + c4];
        *(uint4*)&sA[r * BSTR + c4] = v;
    }
    for (int i = tid; i < 64 * 8; i += 256) {
        int r = i >> 3, c4 = (i & 7) * 4;
        uint4 v = *(const uint4*)&src[(tn * 64 + r) * 32 + c4];
        *(uint4*)&sBt[r * BSTR + c4] = v;
    }
    __syncthreads();

    const int wm = (warp & 3) * 32;     // 4 warps along m (128 rows)
    const int wn = (warp >> 2) * 32;    // 2 warps along n (64 cols)
    const int kq2 = 2 * q;

    float acc[2][4][4];
#pragma unroll
    for (int mt = 0; mt < 2; ++mt)
#pragma unroll
        for (int nt = 0; nt < 4; ++nt)
#pragma unroll
            for (int e = 0; e < 4; ++e) acc[mt][nt][e] = 0.0f;

#pragma unroll
    for (int kc4 = 0; kc4 < 4; ++kc4) {
        const int kp = kc4 * 8 + kq2;
        uint32_t af[2][4], bf[4][2];
#pragma unroll
        for (int mt = 0; mt < 2; ++mt) {
            uint2 la = *(const uint2*)&sA[(wm + mt * 16 + g8)     * BSTR + kp];
            uint2 lb = *(const uint2*)&sA[(wm + mt * 16 + g8 + 8) * BSTR + kp];
            af[mt][0] = la.x;
            af[mt][1] = lb.x;
            af[mt][2] = la.y;
            af[mt][3] = lb.y;
        }
#pragma unroll
        for (int nt = 0; nt < 4; ++nt) {
            uint2 vb = *(const uint2*)&sBt[(wn + nt * 8 + g8) * BSTR + kp];
            bf[nt][0] = vb.x;
            bf[nt][1] = vb.y;
        }
#pragma unroll
        for (int mt = 0; mt < 2; ++mt)
#pragma unroll
            for (int nt = 0; nt < 4; ++nt)
                mma_bf16(acc[mt][nt], af[mt], bf[nt]);
    }

    float* __restrict__ O = out + ((size_t)type * NGRAPH + g) * (NODES * NODES);
#pragma unroll
    for (int mt = 0; mt < 2; ++mt) {
        const int row = tm * 128 + wm + mt * 16 + g8;
#pragma unroll
        for (int nt = 0; nt < 4; ++nt) {
            const int col = tn * 64 + wn + nt * 8 + 2 * q;
            float2 v0, v1;
            v0.x = sigmoid_fast(acc[mt][nt][0]);
            v0.y = sigmoid_fast(acc[mt][nt][1]);
            v1.x = sigmoid_fast(acc[mt][nt][2]);
            v1.y = sigmoid_fast(acc[mt][nt][3]);
            *(float2*)&O[(size_t)row * NODES + col]       = v0;
            *(float2*)&O[(size_t)(row + 8) * NODES + col] = v1;
        }
    }
}

extern "C" void kernel_launch(void* const* d_in, const int* in_sizes, int n_in,
                              void* d_out, int out_size) {
    const float* z   = (const float*)d_in[0];
    // d_in[1] = batch (int64): uniform segments, unused
    const float* Wa1 = (const float*)d_in[2];
    const float* ba1 = (const float*)d_in[3];
    const float* Wa2 = (const float*)d_in[4];
    const float* ba2 = (const float*)d_in[5];
    const float* Wb1 = (const float*)d_in[6];
    const float* bb1 = (const float*)d_in[7];
    const float* Wb2 = (const float*)d_in[8];
    const float* bb2 = (const float*)d_in[9];
    const float* Wt1 = (const float*)d_in[10];
    const float* bt1 = (const float*)d_in[11];
    const float* Wt2 = (const float*)d_in[12];
    const float* bt2 = (const float*)d_in[13];
    float* out = (float*)d_out;

    const int smem1 = (256 * STR + 2 * 64 * STR + 128) * (int)sizeof(float); // 111104
    cudaFuncSetAttribute(mlp_kernel, cudaFuncAttributeMaxDynamicSharedMemorySize, smem1);
    mlp_kernel<<<dim3(NGRAPH, 3), 512, smem1>>>(
        z, Wa1, ba1, Wa2, ba2, Wb1, bb1, Wb2, bb2, Wt1, bt1, Wt2, bt2, out);

    adj_kernel<<<dim3(8, NGRAPH, 3), 256>>>(out);
}

// round 17
// speedup vs baseline: 1.1228x; 1.1228x over previous
#include <cuda_runtime.h>
#include <cstdint>

// Problem constants
#define NGRAPH 128
#define NODES  256
#define CH     64
#define ADJ_ELEMS   ((size_t)NGRAPH * NODES * NODES)   // 8388608
#define F_ELEMS     ((size_t)NGRAPH * NODES * CH)      // 2097152
#define F_BASE      (3 * ADJ_ELEMS)                    // 25165824
#define STR  72   // sZ/sW row stride (floats); LDS.64 conflict-free (see R7)
#define BSTR 40   // sB row stride (u32); 20 8B-words == 4 (mod 16): conflict-free
#define STAGE 132 // staged row stride (floats): STS bank = 8q+g8+4d -> conflict-free

// k-dimension permutation (f32 buffers): (k, k+4) adjacent -> LDS.64.
__device__ __forceinline__ int posk(int k) {
    return (k & ~7) + ((k & 3) << 1) + ((k >> 2) & 1);
}

__device__ __forceinline__ float tf32r(float x) {
    uint32_t u;
    asm("cvt.rna.tf32.f32 %0, %1;" : "=r"(u) : "f"(x));
    return __uint_as_float(u);
}

__device__ __forceinline__ void mma_tf32(float d[4], const uint32_t a[4], const uint32_t b[2]) {
    asm volatile(
        "mma.sync.aligned.m16n8k8.row.col.f32.tf32.tf32.f32 "
        "{%0,%1,%2,%3},{%4,%5,%6,%7},{%8,%9},{%0,%1,%2,%3};\n"
        : "+f"(d[0]), "+f"(d[1]), "+f"(d[2]), "+f"(d[3])
        : "r"(a[0]), "r"(a[1]), "r"(a[2]), "r"(a[3]),
          "r"(b[0]), "r"(b[1]));
}

__device__ __forceinline__ void mma_bf16(float d[4], const uint32_t a[4], const uint32_t b[2]) {
    asm volatile(
        "mma.sync.aligned.m16n8k16.row.col.f32.bf16.bf16.f32 "
        "{%0,%1,%2,%3},{%4,%5,%6,%7},{%8,%9},{%0,%1,%2,%3};\n"
        : "+f"(d[0]), "+f"(d[1]), "+f"(d[2]), "+f"(d[3])
        : "r"(a[0]), "r"(a[1]), "r"(a[2]), "r"(a[3]),
          "r"(b[0]), "r"(b[1]));
}

// sigmoid(x) = 0.5*tanh(x/2)+0.5 — single MUFU.
__device__ __forceinline__ float sigmoid_fast(float x) {
    float t;
    asm("tanh.approx.f32 %0, %1;" : "=f"(t) : "f"(x * 0.5f));
    return fmaf(t, 0.5f, 0.5f);
}

// pack {lo,hi} f32 -> bf16x2 (lo in bits[15:0])
__device__ __forceinline__ uint32_t pack_bf16(float lo, float hi) {
    uint32_t d;
    asm("cvt.rn.bf16x2.f32 %0, %1, %2;" : "=r"(d) : "f"(hi), "f"(lo));
    return d;
}

// ---------------------------------------------------------------------------
// Fused kernel, 512 threads (16 warps), 1 CTA/SM, grid (128,3) = 384 CTAs.
// MLP: R14 path verbatim (F fp32 bit-identical, metric-dominant).
// Adjacency: SYMMETRIC — 3 blocks of 128x128 (B00, B11, B01); B10 = B01^T
//   mirrored through smem staging (dead sZ region). 1536 bf16 MMAs/CTA
//   (was 2048), 25% fewer sigmoids/frag-A-loads.
// smem: sZ [256][STR] f32 (reused as staged [128][STAGE] in mirror phase)
//     + sW [2][64][STR] + bias[128] + sB [256][BSTR] u32 = 152064 B
// ---------------------------------------------------------------------------
__global__ void __launch_bounds__(512, 1) fused_kernel(
    const float* __restrict__ z,
    const float* __restrict__ Wa1, const float* __restrict__ ba1,
    const float* __restrict__ Wa2, const float* __restrict__ ba2,
    const float* __restrict__ Wb1, const float* __restrict__ bb1,
    const float* __restrict__ Wb2, const float* __restrict__ bb2,
    const float* __restrict__ Wt1, const float* __restrict__ bt1,
    const float* __restrict__ Wt2, const float* __restrict__ bt2,
    float* __restrict__ out)
{
    extern __shared__ __align__(16) float smem[];
    float*    sZ    = smem;                    // [256][STR] f32 / staged in phase 3
    float*    sW    = smem + 256 * STR;        // [2][64][STR] tf32 weights
    float*    sBias = sW + 2 * 64 * STR;       // [128]
    uint32_t* sB    = (uint32_t*)(sBias + 128); // [256][BSTR] F as bf16x2 pairs

    const int g    = blockIdx.x;
    const int type = blockIdx.y;

    const float *W1, *B1, *W2, *B2;
    if (type == 0)      { W1 = Wa1; B1 = ba1; W2 = Wa2; B2 = ba2; }
    else if (type == 1) { W1 = Wb1; B1 = bb1; W2 = Wb2; B2 = bb2; }
    else                { W1 = Wt1; B1 = bt1; W2 = Wt2; B2 = bt2; }

    const int tid = threadIdx.x;
    const int warp = tid >> 5, lane = tid & 31;
    const int g8 = lane >> 2, q = lane & 3;

    // ---------------- Phase 0: loads ----------------
    const float* zG = z + (size_t)g * NODES * CH;
    for (int i = tid; i < NODES * CH / 4; i += 512) {       // 4096 float4s
        int r = i >> 4, c4 = (i & 15) * 4;
        float4 v = *(const float4*)&zG[r * CH + c4];
        float* row = &sZ[r * STR];
        row[posk(c4 + 0)] = v.x;
        row[posk(c4 + 1)] = v.y;
        row[posk(c4 + 2)] = v.z;
        row[posk(c4 + 3)] = v.w;
    }
#pragma unroll 1
    for (int l = 0; l < 2; ++l) {
        const float* W = l ? W2 : W1;
        float* w = sW + l * 64 * STR;
        for (int i = tid; i < 64 * 64; i += 512) {
            int k = i >> 6, n = i & 63;
            w[n * STR + posk(k)] = tf32r(W[i]);   // coalesced read, scattered store
        }
    }
    if (tid < 64)       sBias[tid] = B1[tid];
    else if (tid < 128) sBias[tid] = B2[tid - 64];
    __syncthreads();

    // ---------------- Phase 1: MLP (warp-private 16 rows, no block syncs) ----
    const int row0 = warp * 16;
    const int kq2 = 2 * q;
    float* __restrict__ fout = out + F_BASE + (size_t)type * F_ELEMS
                                   + (size_t)g * NODES * CH;

#pragma unroll 1
    for (int l = 0; l < 2; ++l) {
        const float* Wt   = sW + l * 64 * STR;
        const float* bias = sBias + l * 64;

        float acc[8][4];
#pragma unroll
        for (int nt = 0; nt < 8; ++nt)
#pragma unroll
            for (int e = 0; e < 4; ++e) acc[nt][e] = 0.0f;

#pragma unroll
        for (int k0 = 0; k0 < 8; ++k0) {
            const int kp = k0 * 8 + kq2;
            float2 la = *(const float2*)&sZ[(row0 + g8)     * STR + kp];
            float2 lb = *(const float2*)&sZ[(row0 + g8 + 8) * STR + kp];
            uint32_t af[4];
            af[0] = __float_as_uint(tf32r(la.x));
            af[1] = __float_as_uint(tf32r(lb.x));
            af[2] = __float_as_uint(tf32r(la.y));
            af[3] = __float_as_uint(tf32r(lb.y));
#pragma unroll
            for (int nt = 0; nt < 8; ++nt) {
                float2 wb = *(const float2*)&Wt[(nt * 8 + g8) * STR + kp];
                uint32_t bf[2] = {__float_as_uint(wb.x), __float_as_uint(wb.y)};
                mma_tf32(acc[nt], af, bf);
            }
        }
        __syncwarp();   // all lanes done reading this warp's sZ rows

#pragma unroll
        for (int nt = 0; nt < 8; ++nt) {
            const int c0 = nt * 8 + 2 * q;
            float v0 = fmaxf(acc[nt][0] + bias[c0],     0.0f);
            float v1 = fmaxf(acc[nt][1] + bias[c0 + 1], 0.0f);
            float v2 = fmaxf(acc[nt][2] + bias[c0],     0.0f);
            float v3 = fmaxf(acc[nt][3] + bias[c0 + 1], 0.0f);
            if (l == 0) {
                const int p0 = posk(c0), p1 = posk(c0 + 1);
                float* rA = &sZ[(row0 + g8) * STR];
                float* rB = &sZ[(row0 + g8 + 8) * STR];
                rA[p0] = v0; rA[p1] = v1;
                rB[p0] = v2; rB[p1] = v3;
            } else {
                // F: fp32 -> gmem (bit-identical); bf16x2 pair -> sB
                *(float2*)&fout[(size_t)(row0 + g8)     * CH + c0] = make_float2(v0, v1);
                *(float2*)&fout[(size_t)(row0 + g8 + 8) * CH + c0] = make_float2(v2, v3);
                const int p2 = (nt >> 1) * 8 + 2 * q + (nt & 1);
                sB[(row0 + g8)     * BSTR + p2] = pack_bf16(v0, v1);
                sB[(row0 + g8 + 8) * BSTR + p2] = pack_bf16(v2, v3);
            }
        }
        __syncwarp();   // stores visible before next layer's lane-crossed reads
    }
    __syncthreads();    // full F (bf16x2) visible; sZ dead -> staged reuse

    // ---------------- Phase 3: symmetric adjacency, 3 blocks -----------------
    // 16 warps as 4x4 grid of 32x32 warp tiles per 128x128 block.
    const int wr = (warp >> 2) * 32;    // row offset within block
    const int wc = (warp & 3)  * 32;    // col offset within block
    float* __restrict__ staged = sZ;    // [128 cols][STAGE] sigmoid(B01)
    float* __restrict__ O = out + ((size_t)type * NGRAPH + g) * (NODES * NODES);

#pragma unroll 1
    for (int blk = 0; blk < 3; ++blk) {
        // blocks: 0 -> (0,0), 1 -> (1,1), 2 -> (0,1) [B01 last, staged]
        const int bm = (blk == 1) ? 1 : 0;
        const int bn = (blk == 0) ? 0 : 1;

        float acc[2][4][4];
#pragma unroll
        for (int mt = 0; mt < 2; ++mt)
#pragma unroll
            for (int nt = 0; nt < 4; ++nt)
#pragma unroll
                for (int e = 0; e < 4; ++e) acc[mt][nt][e] = 0.0f;

#pragma unroll
        for (int kc4 = 0; kc4 < 4; ++kc4) {
            const int kp = kc4 * 8 + kq2;
            uint32_t af[2][4], bf[4][2];
#pragma unroll
            for (int mt = 0; mt < 2; ++mt) {
                const int ra = bm * 128 + wr + mt * 16 + g8;
                uint2 la = *(const uint2*)&sB[ra       * BSTR + kp];
                uint2 lb = *(const uint2*)&sB[(ra + 8) * BSTR + kp];
                af[mt][0] = la.x;
                af[mt][1] = lb.x;
                af[mt][2] = la.y;
                af[mt][3] = lb.y;
            }
#pragma unroll
            for (int nt = 0; nt < 4; ++nt) {
                uint2 vb = *(const uint2*)&sB[(bn * 128 + wc + nt * 8 + g8) * BSTR + kp];
                bf[nt][0] = vb.x;
                bf[nt][1] = vb.y;
            }
#pragma unroll
            for (int mt = 0; mt < 2; ++mt)
#pragma unroll
                for (int nt = 0; nt < 4; ++nt)
                    mma_bf16(acc[mt][nt], af[mt], bf[nt]);
        }

#pragma unroll
        for (int mt = 0; mt < 2; ++mt) {
            const int rl = wr + mt * 16 + g8;      // local row in block
            const int grow = bm * 128 + rl;
#pragma unroll
            for (int nt = 0; nt < 4; ++nt) {
                const int cl = wc + nt * 8 + 2 * q;  // local col in block
                const int gcol = bn * 128 + cl;
                float s0 = sigmoid_fast(acc[mt][nt][0]);
                float s1 = sigmoid_fast(acc[mt][nt][1]);
                float s2 = sigmoid_fast(acc[mt][nt][2]);
                float s3 = sigmoid_fast(acc[mt][nt][3]);
                *(float2*)&O[(size_t)grow * NODES + gcol]       = make_float2(s0, s1);
                *(float2*)&O[(size_t)(grow + 8) * NODES + gcol] = make_float2(s2, s3);
                if (blk == 2) {
                    // stage transposed: staged[col][row] (STS.32, conflict-free)
                    staged[cl * STAGE + rl]           = s0;
                    staged[(cl + 1) * STAGE + rl]     = s1;
                    staged[cl * STAGE + rl + 8]       = s2;
                    staged[(cl + 1) * STAGE + rl + 8] = s3;
                }
            }
        }
    }
    __syncthreads();   // staged fully written

    // Mirror B10 = B01^T: staged[a][.] is exactly B10 row (128+a), contiguous.
    {
        const int a  = warp * 8 + (lane >> 2);   // 16 warps x 8 rows = 128
        const int b0 = (lane & 3) * 32;          // 4 lanes x 32 cols = 128
        const float* src = staged + a * STAGE + b0;
        float* dst = O + (size_t)(128 + a) * NODES + b0;
#pragma unroll
        for (int j = 0; j < 8; ++j)
            *(float4*)&dst[j * 4] = *(const float4*)&src[j * 4];
    }
}

extern "C" void kernel_launch(void* const* d_in, const int* in_sizes, int n_in,
                              void* d_out, int out_size) {
    const float* z   = (const float*)d_in[0];
    // d_in[1] = batch (int64): uniform segments, unused
    const float* Wa1 = (const float*)d_in[2];
    const float* ba1 = (const float*)d_in[3];
    const float* Wa2 = (const float*)d_in[4];
    const float* ba2 = (const float*)d_in[5];
    const float* Wb1 = (const float*)d_in[6];
    const float* bb1 = (const float*)d_in[7];
    const float* Wb2 = (const float*)d_in[8];
    const float* bb2 = (const float*)d_in[9];
    const float* Wt1 = (const float*)d_in[10];
    const float* bt1 = (const float*)d_in[11];
    const float* Wt2 = (const float*)d_in[12];
    const float* bt2 = (const float*)d_in[13];
    float* out = (float*)d_out;

    const int smem_bytes = (256 * STR + 2 * 64 * STR + 128) * (int)sizeof(float)
                         + 256 * BSTR * (int)sizeof(uint32_t);   // 152064
    cudaFuncSetAttribute(fused_kernel, cudaFuncAttributeMaxDynamicSharedMemorySize, smem_bytes);
    fused_kernel<<<dim3(NGRAPH, 3), 512, smem_bytes>>>(
        z, Wa1, ba1, Wa2, ba2, Wb1, bb1, Wb2, bb2, Wt1, bt1, Wt2, bt2, out);
}